// round 6
// baseline (speedup 1.0000x reference)
#include <cuda_runtime.h>

// Problem constants (fixed by reference: D=64, N=262144)
#define ROWS 129               // 2*D + 1
#define NCOLS 262144           // N
#define STRIDE (NCOLS + 1)     // 262145 floats per row
#define CHUNK 8192
#define CHUNKS_PER_ROW (NCOLS / CHUNK)   // 32
#define BLOCK 256
#define COLS_PER_BLOCK (BLOCK * 4)       // 1024 columns per pass3 block

__device__ float g_partial[ROWS * CHUNKS_PER_ROW];
__device__ float g_t[ROWS];

// ---------------------------------------------------------------------------
// Pass 1 (read-only): partials of s_i = sum_{j<N} Z[i,j] * Z[128,j].
// No stores -> L2 footprint is Z alone, leaving it warm for pass 3.
// ---------------------------------------------------------------------------
__global__ void tf_pass1(const float* __restrict__ Z) {
    const int row = blockIdx.y;                  // 0..128
    const size_t j0 = (size_t)blockIdx.x * CHUNK;

    const float* __restrict__ zr = Z + (size_t)row * STRIDE + j0;
    const float* __restrict__ zl = Z + (size_t)(ROWS - 1) * STRIDE + j0;

    float acc = 0.0f;
    #pragma unroll 8
    for (int j = threadIdx.x; j < CHUNK; j += BLOCK)
        acc = fmaf(zr[j], zl[j], acc);

    __shared__ float sh[BLOCK];
    sh[threadIdx.x] = acc;
    __syncthreads();
    for (int s = BLOCK / 2; s > 0; s >>= 1) {
        if (threadIdx.x < s) sh[threadIdx.x] += sh[threadIdx.x + s];
        __syncthreads();
    }
    if (threadIdx.x == 0) g_partial[row * CHUNKS_PER_ROW + blockIdx.x] = sh[0];
}

// ---------------------------------------------------------------------------
// Pass 2 (tiny, one block): s = reduce(partials); t = Q^T s.
// ---------------------------------------------------------------------------
__global__ void tf_pass2(const float* __restrict__ Q) {
    __shared__ float s_sh[ROWS];
    const int i = threadIdx.x;

    if (i < ROWS) {
        float acc = 0.0f;
        #pragma unroll
        for (int c = 0; c < CHUNKS_PER_ROW; c++)
            acc += g_partial[i * CHUNKS_PER_ROW + c];
        s_sh[i] = acc;
    }
    __syncthreads();

    if (i < ROWS) {
        float acc = 0.0f;
        #pragma unroll 8
        for (int k = 0; k < ROWS; k++)
            acc = fmaf(s_sh[k], Q[k * ROWS + i], acc);
        g_t[i] = acc;
    }
}

// ---------------------------------------------------------------------------
// Pass 3: fused copy + row-128 update.
// For each column j: stream all 129 rows once (mostly L2 hits from pass 1),
// copy rows 0..127 to out, and write out[128,j] = Z[128,j] + (sum_k t_k Z[k,j])/N.
// 4 columns per thread -> 4 accumulators, 16 loads in flight per thread.
// Stores use __stcs (evict-first) so the output stream doesn't evict Z from L2.
// ---------------------------------------------------------------------------
__global__ void tf_pass3(const float* __restrict__ Z, float* __restrict__ out) {
    __shared__ float t_sh[ROWS];
    if (threadIdx.x < ROWS) t_sh[threadIdx.x] = g_t[threadIdx.x];
    __syncthreads();

    const size_t base = (size_t)blockIdx.x * COLS_PER_BLOCK + threadIdx.x;
    const float inv_n = 1.0f / (float)NCOLS;

    if (base + 3 * BLOCK <= (size_t)NCOLS) {
        // fast path: all 4 columns in range
        const float* __restrict__ zp = Z + base;
        float* __restrict__ op = out + base;
        float a0 = 0.f, a1 = 0.f, a2 = 0.f, a3 = 0.f;

        #pragma unroll 4
        for (int k = 0; k < ROWS - 1; k++) {
            const size_t off = (size_t)k * STRIDE;
            float v0 = zp[off];
            float v1 = zp[off + BLOCK];
            float v2 = zp[off + 2 * BLOCK];
            float v3 = zp[off + 3 * BLOCK];
            const float t = t_sh[k];
            a0 = fmaf(t, v0, a0);
            a1 = fmaf(t, v1, a1);
            a2 = fmaf(t, v2, a2);
            a3 = fmaf(t, v3, a3);
            __stcs(op + off, v0);
            __stcs(op + off + BLOCK, v1);
            __stcs(op + off + 2 * BLOCK, v2);
            __stcs(op + off + 3 * BLOCK, v3);
        }
        {
            const size_t off = (size_t)(ROWS - 1) * STRIDE;
            const float t = t_sh[ROWS - 1];
            float v0 = zp[off];
            float v1 = zp[off + BLOCK];
            float v2 = zp[off + 2 * BLOCK];
            float v3 = zp[off + 3 * BLOCK];
            a0 = fmaf(t, v0, a0);
            a1 = fmaf(t, v1, a1);
            a2 = fmaf(t, v2, a2);
            a3 = fmaf(t, v3, a3);
            __stcs(op + off,             v0 + a0 * inv_n);
            __stcs(op + off + BLOCK,     v1 + a1 * inv_n);
            __stcs(op + off + 2 * BLOCK, v2 + a2 * inv_n);
            __stcs(op + off + 3 * BLOCK, v3 + a3 * inv_n);
        }
    } else {
        // tail path (last block only): per-column bounds checks, j <= NCOLS inclusive
        #pragma unroll
        for (int c = 0; c < 4; c++) {
            const size_t j = base + (size_t)c * BLOCK;
            if (j > (size_t)NCOLS) continue;
            float acc = 0.f;
            for (int k = 0; k < ROWS - 1; k++) {
                float v = Z[(size_t)k * STRIDE + j];
                acc = fmaf(t_sh[k], v, acc);
                __stcs(&out[(size_t)k * STRIDE + j], v);
            }
            float v = Z[(size_t)(ROWS - 1) * STRIDE + j];
            acc = fmaf(t_sh[ROWS - 1], v, acc);
            __stcs(&out[(size_t)(ROWS - 1) * STRIDE + j], v + acc * inv_n);
        }
    }
}

extern "C" void kernel_launch(void* const* d_in, const int* in_sizes, int n_in,
                              void* d_out, int out_size) {
    const float* Z = (const float*)d_in[0];
    // d_in[1] is P: structurally a single 1 at [-1,-1] (exploited analytically)
    const float* Q = (const float*)d_in[2];
    float* out = (float*)d_out;

    dim3 g1(CHUNKS_PER_ROW, ROWS);
    tf_pass1<<<g1, BLOCK>>>(Z);
    tf_pass2<<<1, BLOCK>>>(Q);
    const int total_cols = NCOLS + 1;
    tf_pass3<<<(total_cols + COLS_PER_BLOCK - 1) / COLS_PER_BLOCK, BLOCK>>>(Z, out);
}

// round 7
// speedup vs baseline: 1.2224x; 1.2224x over previous
#include <cuda_runtime.h>

// Problem constants (fixed by reference: D=64, N=262144)
#define ROWS 129
#define NCOLS 262144
#define STRIDE (NCOLS + 1)      // 262145 floats per row (odd!)
#define LASTROW 128

#define BLOCK 256
#define CHUNK1 4096
#define NCH1 (NCOLS / CHUNK1)   // 64
#define CHUNK3 1024
#define NCH3 (NCOLS / CHUNK3)   // 256
#define PROW (NCOLS + 16)       // padded partial-row length

__device__ float g_partial[ROWS * NCH1];
__device__ float g_t[ROWS];
__device__ __align__(16) float g_p[4 * PROW];   // 4 group partial rows

// ---------------------------------------------------------------------------
// Pass 1: fused copy (out = Z) + dot partials s_i = sum_{j<N} Z[i,j]*Z[128,j].
// Per-row alignment peel -> aligned float4 body. Row 128 staged (shifted) in
// smem so dot reads are aligned LDS.128. Stores are evict-first (__stcs).
// ---------------------------------------------------------------------------
__global__ void tf_pass1(const float* __restrict__ Z, float* __restrict__ out) {
    const int row = blockIdx.y;
    const int tid = threadIdx.x;
    const size_t c0 = (size_t)blockIdx.x * CHUNK1;
    const int r = row & 3;
    const int p = (4 - r) & 3;              // peel so row base + c0 + p is 16B aligned
    const int tail = (CHUNK1 - p) & 3;
    const int body = CHUNK1 - p - tail;
    const int nv4 = body >> 2;

    const float* __restrict__ z128 = Z + (size_t)LASTROW * STRIDE;

    __shared__ __align__(16) float zl_sh[CHUNK1];
    __shared__ float warp_acc[BLOCK / 32];

    // stage z128[c0+p .. c0+p+body) shifted to index 0 (coalesced scalar, L2-hot)
    for (int x = tid; x < body; x += BLOCK)
        zl_sh[x] = __ldg(z128 + c0 + p + x);
    __syncthreads();

    const float4* __restrict__ zr4 = (const float4*)(Z + (size_t)row * STRIDE + c0 + p);
    float4* __restrict__ o4 = (float4*)(out + (size_t)row * STRIDE + c0 + p);
    const float4* zs4 = (const float4*)zl_sh;

    float acc = 0.0f;
    #pragma unroll
    for (int it = 0; it < CHUNK1 / 4 / BLOCK; it++) {
        const int idx = tid + BLOCK * it;
        if (idx < nv4) {
            float4 v = zr4[idx];
            float4 w = zs4[idx];
            acc = fmaf(v.x, w.x, acc);
            acc = fmaf(v.y, w.y, acc);
            acc = fmaf(v.z, w.z, acc);
            acc = fmaf(v.w, w.w, acc);
            __stcs(o4 + idx, v);
        }
    }
    // head (p elems) and tail elems, scalar
    if (tid < p) {
        const size_t col = c0 + tid;
        const float v = Z[(size_t)row * STRIDE + col];
        acc = fmaf(v, __ldg(z128 + col), acc);
        __stcs(out + (size_t)row * STRIDE + col, v);
    }
    if (tid >= 8 && tid < 8 + tail) {
        const size_t col = c0 + p + body + (tid - 8);
        const float v = Z[(size_t)row * STRIDE + col];
        acc = fmaf(v, __ldg(z128 + col), acc);
        __stcs(out + (size_t)row * STRIDE + col, v);
    }

    // deterministic reduction: warp shuffles -> 8 values -> warp 0
    for (int o = 16; o; o >>= 1) acc += __shfl_down_sync(0xffffffffu, acc, o);
    if ((tid & 31) == 0) warp_acc[tid >> 5] = acc;
    __syncthreads();
    if (tid < 8) {
        float a = warp_acc[tid];
        for (int o = 4; o; o >>= 1) a += __shfl_down_sync(0xffu, a, o, 8);
        if (tid == 0) g_partial[row * NCH1 + blockIdx.x] = a;
    }
}

// ---------------------------------------------------------------------------
// Pass 2 (tiny): s = reduce(partials); t = Q^T s; copy last column of Z.
// ---------------------------------------------------------------------------
__global__ void tf_pass2(const float* __restrict__ Z, const float* __restrict__ Q,
                         float* __restrict__ out) {
    __shared__ float s_sh[ROWS];
    const int i = threadIdx.x;
    if (i < ROWS) {
        float a = 0.0f;
        #pragma unroll
        for (int c = 0; c < NCH1; c++) a += g_partial[i * NCH1 + c];
        s_sh[i] = a;
        out[(size_t)i * STRIDE + NCOLS] = Z[(size_t)i * STRIDE + NCOLS];
    }
    __syncthreads();
    if (i < ROWS) {
        float a = 0.0f;
        #pragma unroll 8
        for (int k = 0; k < ROWS; k++) a = fmaf(s_sh[k], Q[k * ROWS + i], a);
        g_t[i] = a;
    }
}

// ---------------------------------------------------------------------------
// Pass 3a: row-parallel weighted row-sum. Group g handles rows k == g (mod 4),
// which all share the same alignment shift -> aligned float4 loads with fixed
// per-thread column ownership (register accumulators, deterministic).
// Window for group g is shifted by -g; boundary columns patched in pass3b.
// ---------------------------------------------------------------------------
__global__ void tf_pass3a(const float* __restrict__ Z) {
    const int g = blockIdx.y;                         // 0..3
    const int tid = threadIdx.x;
    const long w0 = (long)blockIdx.x * CHUNK3 - g;    // window start column

    __shared__ float t_sh[ROWS];
    if (tid < ROWS) t_sh[tid] = g_t[tid];
    __syncthreads();

    float a0 = 0.f, a1 = 0.f, a2 = 0.f, a3 = 0.f;
    #pragma unroll 4
    for (int rr = 0; rr < 32; rr++) {
        const int k = g + 4 * rr;                     // g .. g+124 (<=127)
        const float4* zp = (const float4*)(Z + ((long)k * STRIDE + w0));
        const float4 v = zp[tid];
        const float t = t_sh[k];
        a0 = fmaf(t, v.x, a0);
        a1 = fmaf(t, v.y, a1);
        a2 = fmaf(t, v.z, a2);
        a3 = fmaf(t, v.w, a3);
    }
    if (g == 0) {                                     // row 128 belongs to group 0
        const float4* zp = (const float4*)(Z + ((long)LASTROW * STRIDE + w0));
        const float4 v = zp[tid];
        const float t = t_sh[LASTROW];
        a0 = fmaf(t, v.x, a0);
        a1 = fmaf(t, v.y, a1);
        a2 = fmaf(t, v.z, a2);
        a3 = fmaf(t, v.w, a3);
    }
    // p_g index base 4+g makes (4+g+w0) % 4 == 0 -> aligned float4 store
    float4* pp = (float4*)(g_p + (long)g * PROW + (4 + g) + w0 + 4 * (long)tid);
    *pp = make_float4(a0, a1, a2, a3);
}

// ---------------------------------------------------------------------------
// Pass 3b: out[128,j] = Z[128,j] + (p0+p1+p2+p3)[j] / N for j < N-3.
// Last block: columns N-3..N computed directly (one warp each, shfl-reduce).
// ---------------------------------------------------------------------------
__global__ void tf_pass3b(const float* __restrict__ Z, float* __restrict__ out) {
    const float inv_n = 1.0f / (float)NCOLS;
    if (blockIdx.x < gridDim.x - 1) {
        const size_t j = (size_t)blockIdx.x * BLOCK + threadIdx.x;
        if (j < (size_t)NCOLS - 3) {
            const float s = g_p[0 * PROW + 4 + 0 + j]
                          + g_p[1 * PROW + 5 + j]
                          + g_p[2 * PROW + 6 + j]
                          + g_p[3 * PROW + 7 + j];
            const size_t o = (size_t)LASTROW * STRIDE + j;
            out[o] = Z[o] + s * inv_n;
        }
        return;
    }
    // special columns NCOLS-3 .. NCOLS (4 cols), one warp each
    const int w = threadIdx.x >> 5;
    const int lane = threadIdx.x & 31;
    if (w < 4) {
        const size_t jj = (size_t)NCOLS - 3 + w;
        float a = 0.0f;
        for (int k = lane; k < ROWS; k += 32)
            a = fmaf(g_t[k], Z[(size_t)k * STRIDE + jj], a);
        for (int o = 16; o; o >>= 1) a += __shfl_down_sync(0xffffffffu, a, o);
        if (lane == 0) {
            const size_t oo = (size_t)LASTROW * STRIDE + jj;
            out[oo] = Z[oo] + a * inv_n;
        }
    }
}

extern "C" void kernel_launch(void* const* d_in, const int* in_sizes, int n_in,
                              void* d_out, int out_size) {
    const float* Z = (const float*)d_in[0];
    // d_in[1] is P: structurally a single 1 at [-1,-1] (exploited analytically)
    const float* Q = (const float*)d_in[2];
    float* out = (float*)d_out;

    dim3 g1(NCH1, ROWS);            // 64 x 129 = 8256 blocks
    tf_pass1<<<g1, BLOCK>>>(Z, out);
    tf_pass2<<<1, BLOCK>>>(Z, Q, out);
    dim3 g3(NCH3, 4);               // 256 x 4 = 1024 blocks
    tf_pass3a<<<g3, BLOCK>>>(Z);
    tf_pass3b<<<NCOLS / BLOCK + 1, BLOCK>>>(Z, out);
}